// round 2
// baseline (speedup 1.0000x reference)
#include <cuda_runtime.h>
#include <cstdint>

// Problem constants
#define BH   128       // B*H = 8*16
#define SEQ  1024
#define DIM  64
#define QT   128       // q rows per CTA
#define KT   128       // k rows per iteration
#define NIT  (SEQ/KT)  // 8

// Scratch for log_sigmoid(V): 128*1024*64 floats = 33.5 MB
__device__ float g_L[BH * SEQ * DIM];
// Mask encoding: 0 = 1-byte bool, 1 = 4-byte (int32 or float32 0/1)
__device__ int g_mask_mode;

// ---------------- packed f32x2 helpers ----------------
__device__ __forceinline__ unsigned long long pack2(float x) {
    unsigned long long r;
    unsigned u = __float_as_uint(x);
    asm("mov.b64 %0, {%1,%2};" : "=l"(r) : "r"(u), "r"(u));
    return r;
}
__device__ __forceinline__ unsigned long long pack2f(float lo, float hi) {
    unsigned long long r;
    unsigned a = __float_as_uint(lo), b = __float_as_uint(hi);
    asm("mov.b64 %0, {%1,%2};" : "=l"(r) : "r"(a), "r"(b));
    return r;
}
__device__ __forceinline__ void fma2(unsigned long long& d,
                                     unsigned long long a,
                                     unsigned long long b) {
    asm("fma.rn.f32x2 %0, %1, %2, %3;" : "=l"(d) : "l"(a), "l"(b), "l"(d));
}
__device__ __forceinline__ float2 unpk(unsigned long long v) {
    unsigned lo, hi;
    asm("mov.b64 {%0,%1}, %2;" : "=r"(lo), "=r"(hi) : "l"(v));
    return make_float2(__uint_as_float(lo), __uint_as_float(hi));
}

// ---------------- mask dtype detector ----------------
// Inspect the first 1024 32-bit words of the mask buffer.
// int32 bool:  every word is 0 or 1.
// float32 0/1: every word is 0 or 0x3F800000.
// uint8 bool:  words are random 4-byte packings of 0/1 -> neither holds.
__global__ void mask_detect_kernel(const unsigned int* __restrict__ m) {
    int t = threadIdx.x;
    int wide_ok = 1;
#pragma unroll
    for (int i = 0; i < 4; i++) {
        unsigned int w = m[t * 4 + i];
        if (!(w == 0u || w == 1u || w == 0x3F800000u)) wide_ok = 0;
    }
    int all_wide = __syncthreads_and(wide_ok);
    if (t == 0) g_mask_mode = all_wide ? 1 : 0;
}

// ---------------- preprocess: L = log_sigmoid(V) ----------------
__global__ void logsig_kernel(const float4* __restrict__ v) {
    int i = blockIdx.x * 256 + threadIdx.x;   // grid sized exactly: BH*SEQ*DIM/4 elements
    float4 x = v[i];
    float4 y;
    y.x = fminf(x.x, 0.f) - log1pf(__expf(-fabsf(x.x)));
    y.y = fminf(x.y, 0.f) - log1pf(__expf(-fabsf(x.y)));
    y.z = fminf(x.z, 0.f) - log1pf(__expf(-fabsf(x.z)));
    y.w = fminf(x.w, 0.f) - log1pf(__expf(-fabsf(x.w)));
    ((float4*)g_L)[i] = y;
}

// ---------------- smem layout (floats) ----------------
// sQ : [64][128]  Q transposed (d-major), pre-scaled by 1/8        ->  8192 f
// sK : [64][128]  K tile transposed (d-major)                      ->  8192 f
// sP : [128][132] P transposed ([k][q], padded stride 132)         -> 16896 f
// sL : [128][64]  log-sigmoid V tile, natural layout               ->  8192 f
// sM : 128*128 bytes mask tile                                     ->  4096 f
// sDen: [128] running softmax denominators                         ->   128 f
#define OFF_Q  0
#define OFF_K  8192
#define OFF_P  16384
#define OFF_L  33280
#define OFF_M  41472
#define OFF_D  45568
#define SMEM_FLOATS 45696
#define SMEM_BYTES  (SMEM_FLOATS * 4)   // 182784

__global__ void __launch_bounds__(256, 1)
attn_kernel(const float* __restrict__ Q,
            const float* __restrict__ K,
            const unsigned char* __restrict__ M,
            float* __restrict__ out) {
    extern __shared__ float sm[];
    float* sQ = sm + OFF_Q;
    float* sK = sm + OFF_K;
    float* sP = sm + OFF_P;
    float* sL = sm + OFF_L;
    unsigned char* sM = (unsigned char*)(sm + OFF_M);
    float* sDen = sm + OFF_D;

    const int t  = threadIdx.x;
    const int bh = blockIdx.y;          // 0..127
    const int q0 = blockIdx.x * QT;     // q tile base
    const int mask_mode = g_mask_mode;

    const float* Qb = Q + ((size_t)bh * SEQ + q0) * DIM;
    const float* Kb = K + (size_t)bh * SEQ * DIM;
    const float* Lb = g_L + (size_t)bh * SEQ * DIM;
    // batch index = bh / H = bh >> 4 (H = 16); mask shape [B,1,S,S]
    const size_t mrow0 = ((size_t)(bh >> 4) * SEQ + q0) * SEQ;

    // ---- load Q (transpose, fold 1/sqrt(64)) ----
    {
        int q = t >> 1, h2 = t & 1;
        const float4* src = (const float4*)(Qb + q * DIM + h2 * 32);
#pragma unroll
        for (int i = 0; i < 8; i++) {
            float4 v = src[i];
            int d = h2 * 32 + i * 4;
            sQ[(d + 0) * 128 + q] = v.x * 0.125f;
            sQ[(d + 1) * 128 + q] = v.y * 0.125f;
            sQ[(d + 2) * 128 + q] = v.z * 0.125f;
            sQ[(d + 3) * 128 + q] = v.w * 0.125f;
        }
    }
    if (t < 128) sDen[t] = 0.f;

    // stage-1 thread mapping: 16x16 grid; 8 contiguous rows, 8 cols strided by 16
    const int rg = t >> 4, cg = t & 15;
    const int r0 = rg * 8;
    // stage-2 mapping: 2 k-slices x (16x8); 8 contiguous rows, 8 cols strided by 8
    const int sl = t >> 7, u = t & 127;
    const int cg2 = u & 7, rg2 = u >> 3;
    const int r20 = rg2 * 8;

    unsigned long long acc2[4][8];   // O accumulator: row-pairs x 8 cols
#pragma unroll
    for (int a = 0; a < 4; a++)
#pragma unroll
        for (int b = 0; b < 8; b++) acc2[a][b] = 0ull;

    for (int it = 0; it < NIT; it++) {
        const int k0 = it * KT;
        __syncthreads();   // previous iteration's stage2 readers done

        // ---- load K tile (transpose) ----
        {
            int c = t >> 1, h2 = t & 1;
            const float4* src = (const float4*)(Kb + (size_t)(k0 + c) * DIM + h2 * 32);
#pragma unroll
            for (int i = 0; i < 8; i++) {
                float4 v = src[i];
                int d = h2 * 32 + i * 4;
                sK[(d + 0) * 128 + c] = v.x;
                sK[(d + 1) * 128 + c] = v.y;
                sK[(d + 2) * 128 + c] = v.z;
                sK[(d + 3) * 128 + c] = v.w;
            }
        }
        // ---- load L tile (contiguous) ----
        {
            const float4* src = (const float4*)(Lb + (size_t)k0 * DIM);
            float4* dst = (float4*)sL;
#pragma unroll
            for (int i = 0; i < 8; i++) dst[t + 256 * i] = src[t + 256 * i];
        }
        // ---- load mask tile (dtype-adaptive) ----
        {
            int r = t >> 1, h2 = t & 1;
            if (mask_mode == 0) {
                // 1-byte bool: row stride = SEQ bytes
                const uint4* src = (const uint4*)(M + mrow0 + (size_t)r * SEQ + k0 + h2 * 64);
                uint4* dst = (uint4*)(sM + r * 128 + h2 * 64);
                dst[0] = src[0]; dst[1] = src[1]; dst[2] = src[2]; dst[3] = src[3];
            } else {
                // 4-byte elements (int32 or float32 0/1): nonzero word -> true
                const uint4* src = (const uint4*)((const unsigned int*)M +
                                   mrow0 + (size_t)r * SEQ + k0 + h2 * 64);
                uchar4* dst = (uchar4*)(sM + r * 128 + h2 * 64);
#pragma unroll
                for (int i = 0; i < 16; i++) {
                    uint4 w = src[i];
                    uchar4 b;
                    b.x = w.x ? 1 : 0; b.y = w.y ? 1 : 0;
                    b.z = w.z ? 1 : 0; b.w = w.w ? 1 : 0;
                    dst[i] = b;
                }
            }
        }
        __syncthreads();

        // ---- stage 1: S = (Q/8) @ K^T, P = mask*exp(S), store transposed ----
        {
            unsigned long long acc1[4][8];
#pragma unroll
            for (int a = 0; a < 4; a++)
#pragma unroll
                for (int b = 0; b < 8; b++) acc1[a][b] = 0ull;

#pragma unroll 4
            for (int d = 0; d < 64; d++) {
                const ulonglong2 qa = *(const ulonglong2*)(sQ + d * 128 + r0);
                const ulonglong2 qb = *(const ulonglong2*)(sQ + d * 128 + r0 + 4);
                const unsigned long long a0 = qa.x, a1 = qa.y, a2 = qb.x, a3 = qb.y;
#pragma unroll
                for (int j = 0; j < 8; j++) {
                    unsigned long long bb = pack2(sK[d * 128 + cg + 16 * j]);
                    fma2(acc1[0][j], a0, bb);
                    fma2(acc1[1][j], a1, bb);
                    fma2(acc1[2][j], a2, bb);
                    fma2(acc1[3][j], a3, bb);
                }
            }
            // exp + mask + store P^T (64-bit stores of natural row pairs)
#pragma unroll
            for (int rp = 0; rp < 4; rp++) {
#pragma unroll
                for (int j = 0; j < 8; j++) {
                    float2 sv = unpk(acc1[rp][j]);
                    int c = cg + 16 * j;
                    int r = r0 + 2 * rp;
                    float p0 = sM[r * 128 + c]       ? __expf(sv.x) : 0.f;
                    float p1 = sM[(r + 1) * 128 + c] ? __expf(sv.y) : 0.f;
                    *(unsigned long long*)(sP + c * 132 + r) = pack2f(p0, p1);
                }
            }
        }
        __syncthreads();

        // ---- denominator partial sums (warps 0-3 only) ----
        if (t < 128) {
            float s0 = 0.f, s1 = 0.f, s2 = 0.f, s3 = 0.f;
#pragma unroll 4
            for (int c = 0; c < 128; c += 4) {
                s0 += sP[(c + 0) * 132 + t];
                s1 += sP[(c + 1) * 132 + t];
                s2 += sP[(c + 2) * 132 + t];
                s3 += sP[(c + 3) * 132 + t];
            }
            sDen[t] += (s0 + s1) + (s2 + s3);
        }

        // ---- stage 2: O += P @ L (each slice covers 64 k's) ----
        {
            const int kb = sl * 64;
#pragma unroll 2
            for (int kk = 0; kk < 64; kk++) {
                const int kg = kb + kk;
                const ulonglong2 pa = *(const ulonglong2*)(sP + kg * 132 + r20);
                const ulonglong2 pb = *(const ulonglong2*)(sP + kg * 132 + r20 + 4);
                const unsigned long long a0 = pa.x, a1 = pa.y, a2 = pb.x, a3 = pb.y;
#pragma unroll
                for (int j = 0; j < 8; j++) {
                    unsigned long long bb = pack2(sL[kg * 64 + cg2 + 8 * j]);
                    fma2(acc2[0][j], a0, bb);
                    fma2(acc2[1][j], a1, bb);
                    fma2(acc2[2][j], a2, bb);
                    fma2(acc2[3][j], a3, bb);
                }
            }
        }
    }

    // ---- epilogue: combine k-slices, normalize, exp, store ----
    __syncthreads();
    float* osc = sP;   // reuse, stride 68
    if (sl == 1) {
#pragma unroll
        for (int rp = 0; rp < 4; rp++) {
#pragma unroll
            for (int j = 0; j < 8; j++) {
                float2 v = unpk(acc2[rp][j]);
                int r = r20 + 2 * rp;
                int c = cg2 + 8 * j;
                osc[r * 68 + c]       = v.x;
                osc[(r + 1) * 68 + c] = v.y;
            }
        }
    }
    __syncthreads();
    if (sl == 0) {
#pragma unroll
        for (int rp = 0; rp < 4; rp++) {
#pragma unroll
            for (int j = 0; j < 8; j++) {
                float2 v = unpk(acc2[rp][j]);
                int r = r20 + 2 * rp;
                int c = cg2 + 8 * j;
                float o0 = __expf((v.x + osc[r * 68 + c]) / sDen[r]);
                float o1 = __expf((v.y + osc[(r + 1) * 68 + c]) / sDen[r + 1]);
                out[((size_t)bh * SEQ + q0 + r) * DIM + c]     = o0;
                out[((size_t)bh * SEQ + q0 + r + 1) * DIM + c] = o1;
            }
        }
    }
}

extern "C" void kernel_launch(void* const* d_in, const int* in_sizes, int n_in,
                              void* d_out, int out_size) {
    const float* Q = (const float*)d_in[0];
    const float* K = (const float*)d_in[1];
    const float* V = (const float*)d_in[2];
    const unsigned char* M = (const unsigned char*)d_in[3];
    float* out = (float*)d_out;

    // 0) detect mask element width (bool byte vs int32/float32 widened)
    mask_detect_kernel<<<1, 256>>>((const unsigned int*)M);

    // 1) L = log_sigmoid(V): BH*SEQ*DIM/4 = 2097152 float4 -> 8192 blocks x 256
    logsig_kernel<<<8192, 256>>>((const float4*)V);

    // 2) attention: grid = (q tiles, batch*heads)
    cudaFuncSetAttribute(attn_kernel,
                         cudaFuncAttributeMaxDynamicSharedMemorySize, SMEM_BYTES);
    dim3 grid(SEQ / QT, BH);
    attn_kernel<<<grid, 256, SMEM_BYTES>>>(Q, K, M, out);
}

// round 3
// speedup vs baseline: 1.0014x; 1.0014x over previous
#include <cuda_runtime.h>
#include <cstdint>

// Problem constants
#define BH   128       // B*H = 8*16
#define SEQ  1024
#define DIM  64
#define QT   128       // q rows per CTA
#define KT   128       // k rows per iteration
#define NIT  (SEQ/KT)  // 8

// Scratch for log_sigmoid(V): 128*1024*64 floats = 33.5 MB
__device__ float g_L[BH * SEQ * DIM];
// Mask encoding: 0 = 1-byte bool, 1 = 4-byte (int32 or float32 0/1)
__device__ int g_mask_mode;

// ---------------- packed f32x2 helpers ----------------
__device__ __forceinline__ unsigned long long pack2(float x) {
    unsigned long long r;
    unsigned u = __float_as_uint(x);
    asm("mov.b64 %0, {%1,%2};" : "=l"(r) : "r"(u), "r"(u));
    return r;
}
__device__ __forceinline__ unsigned long long pack2f(float lo, float hi) {
    unsigned long long r;
    unsigned a = __float_as_uint(lo), b = __float_as_uint(hi);
    asm("mov.b64 %0, {%1,%2};" : "=l"(r) : "r"(a), "r"(b));
    return r;
}
__device__ __forceinline__ void fma2(unsigned long long& d,
                                     unsigned long long a,
                                     unsigned long long b) {
    asm("fma.rn.f32x2 %0, %1, %2, %3;" : "=l"(d) : "l"(a), "l"(b), "l"(d));
}
__device__ __forceinline__ float2 unpk(unsigned long long v) {
    unsigned lo, hi;
    asm("mov.b64 {%0,%1}, %2;" : "=r"(lo), "=r"(hi) : "l"(v));
    return make_float2(__uint_as_float(lo), __uint_as_float(hi));
}

// ---------------- mask dtype detector ----------------
// Inspect the first 1024 32-bit words of the mask buffer.
// int32 bool:  every word is 0 or 1.
// float32 0/1: every word is 0 or 0x3F800000.
// uint8 bool:  words are random 4-byte packings of 0/1 -> neither holds.
__global__ void mask_detect_kernel(const unsigned int* __restrict__ m) {
    int t = threadIdx.x;
    int wide_ok = 1;
#pragma unroll
    for (int i = 0; i < 4; i++) {
        unsigned int w = m[t * 4 + i];
        if (!(w == 0u || w == 1u || w == 0x3F800000u)) wide_ok = 0;
    }
    int all_wide = __syncthreads_and(wide_ok);
    if (t == 0) g_mask_mode = all_wide ? 1 : 0;
}

// ---------------- preprocess: L = log_sigmoid(V) ----------------
__global__ void logsig_kernel(const float4* __restrict__ v) {
    int i = blockIdx.x * 256 + threadIdx.x;   // grid sized exactly: BH*SEQ*DIM/4 elements
    float4 x = v[i];
    float4 y;
    y.x = fminf(x.x, 0.f) - log1pf(__expf(-fabsf(x.x)));
    y.y = fminf(x.y, 0.f) - log1pf(__expf(-fabsf(x.y)));
    y.z = fminf(x.z, 0.f) - log1pf(__expf(-fabsf(x.z)));
    y.w = fminf(x.w, 0.f) - log1pf(__expf(-fabsf(x.w)));
    ((float4*)g_L)[i] = y;
}

// ---------------- smem layout (floats) ----------------
// sQ : [64][128]  Q transposed (d-major), pre-scaled by 1/8        ->  8192 f
// sK : [64][128]  K tile transposed (d-major)                      ->  8192 f
// sP : [128][132] P transposed ([k][q], padded stride 132)         -> 16896 f
// sL : [128][64]  log-sigmoid V tile, natural layout               ->  8192 f
// sM : 128*128 bytes mask tile                                     ->  4096 f
// sDen: [128] running softmax denominators                         ->   128 f
#define OFF_Q  0
#define OFF_K  8192
#define OFF_P  16384
#define OFF_L  33280
#define OFF_M  41472
#define OFF_D  45568
#define SMEM_FLOATS 45696
#define SMEM_BYTES  (SMEM_FLOATS * 4)   // 182784

__global__ void __launch_bounds__(256, 1)
attn_kernel(const float* __restrict__ Q,
            const float* __restrict__ K,
            const unsigned char* __restrict__ M,
            float* __restrict__ out) {
    extern __shared__ float sm[];
    float* sQ = sm + OFF_Q;
    float* sK = sm + OFF_K;
    float* sP = sm + OFF_P;
    float* sL = sm + OFF_L;
    unsigned char* sM = (unsigned char*)(sm + OFF_M);
    float* sDen = sm + OFF_D;

    const int t  = threadIdx.x;
    const int bh = blockIdx.y;          // 0..127
    const int q0 = blockIdx.x * QT;     // q tile base
    const int mask_mode = g_mask_mode;

    const float* Qb = Q + ((size_t)bh * SEQ + q0) * DIM;
    const float* Kb = K + (size_t)bh * SEQ * DIM;
    const float* Lb = g_L + (size_t)bh * SEQ * DIM;
    // batch index = bh / H = bh >> 4 (H = 16); mask shape [B,1,S,S]
    const size_t mrow0 = ((size_t)(bh >> 4) * SEQ + q0) * SEQ;

    // ---- load Q (transpose, fold 1/sqrt(64)) ----
    {
        int q = t >> 1, h2 = t & 1;
        const float4* src = (const float4*)(Qb + q * DIM + h2 * 32);
#pragma unroll
        for (int i = 0; i < 8; i++) {
            float4 v = src[i];
            int d = h2 * 32 + i * 4;
            sQ[(d + 0) * 128 + q] = v.x * 0.125f;
            sQ[(d + 1) * 128 + q] = v.y * 0.125f;
            sQ[(d + 2) * 128 + q] = v.z * 0.125f;
            sQ[(d + 3) * 128 + q] = v.w * 0.125f;
        }
    }
    if (t < 128) sDen[t] = 0.f;

    // stage-1 thread mapping: 16x16 grid; 8 contiguous rows, 8 cols strided by 16
    const int rg = t >> 4, cg = t & 15;
    const int r0 = rg * 8;
    // stage-2 mapping: 2 k-slices x (16x8); 8 contiguous rows, 8 cols strided by 8
    const int sl = t >> 7, u = t & 127;
    const int cg2 = u & 7, rg2 = u >> 3;
    const int r20 = rg2 * 8;

    unsigned long long acc2[4][8];   // O accumulator: row-pairs x 8 cols
#pragma unroll
    for (int a = 0; a < 4; a++)
#pragma unroll
        for (int b = 0; b < 8; b++) acc2[a][b] = 0ull;

    for (int it = 0; it < NIT; it++) {
        const int k0 = it * KT;
        __syncthreads();   // previous iteration's stage2 readers done

        // ---- load K tile (transpose) ----
        {
            int c = t >> 1, h2 = t & 1;
            const float4* src = (const float4*)(Kb + (size_t)(k0 + c) * DIM + h2 * 32);
#pragma unroll
            for (int i = 0; i < 8; i++) {
                float4 v = src[i];
                int d = h2 * 32 + i * 4;
                sK[(d + 0) * 128 + c] = v.x;
                sK[(d + 1) * 128 + c] = v.y;
                sK[(d + 2) * 128 + c] = v.z;
                sK[(d + 3) * 128 + c] = v.w;
            }
        }
        // ---- load L tile (contiguous) ----
        {
            const float4* src = (const float4*)(Lb + (size_t)k0 * DIM);
            float4* dst = (float4*)sL;
#pragma unroll
            for (int i = 0; i < 8; i++) dst[t + 256 * i] = src[t + 256 * i];
        }
        // ---- load mask tile (dtype-adaptive) ----
        {
            int r = t >> 1, h2 = t & 1;
            if (mask_mode == 0) {
                // 1-byte bool: row stride = SEQ bytes
                const uint4* src = (const uint4*)(M + mrow0 + (size_t)r * SEQ + k0 + h2 * 64);
                uint4* dst = (uint4*)(sM + r * 128 + h2 * 64);
                dst[0] = src[0]; dst[1] = src[1]; dst[2] = src[2]; dst[3] = src[3];
            } else {
                // 4-byte elements (int32 or float32 0/1): nonzero word -> true
                const uint4* src = (const uint4*)((const unsigned int*)M +
                                   mrow0 + (size_t)r * SEQ + k0 + h2 * 64);
                uchar4* dst = (uchar4*)(sM + r * 128 + h2 * 64);
#pragma unroll
                for (int i = 0; i < 16; i++) {
                    uint4 w = src[i];
                    uchar4 b;
                    b.x = w.x ? 1 : 0; b.y = w.y ? 1 : 0;
                    b.z = w.z ? 1 : 0; b.w = w.w ? 1 : 0;
                    dst[i] = b;
                }
            }
        }
        __syncthreads();

        // ---- stage 1: S = (Q/8) @ K^T, P = mask*exp(S), store transposed ----
        {
            unsigned long long acc1[4][8];
#pragma unroll
            for (int a = 0; a < 4; a++)
#pragma unroll
                for (int b = 0; b < 8; b++) acc1[a][b] = 0ull;

#pragma unroll 4
            for (int d = 0; d < 64; d++) {
                const ulonglong2 qa = *(const ulonglong2*)(sQ + d * 128 + r0);
                const ulonglong2 qb = *(const ulonglong2*)(sQ + d * 128 + r0 + 4);
                const unsigned long long a0 = qa.x, a1 = qa.y, a2 = qb.x, a3 = qb.y;
#pragma unroll
                for (int j = 0; j < 8; j++) {
                    unsigned long long bb = pack2(sK[d * 128 + cg + 16 * j]);
                    fma2(acc1[0][j], a0, bb);
                    fma2(acc1[1][j], a1, bb);
                    fma2(acc1[2][j], a2, bb);
                    fma2(acc1[3][j], a3, bb);
                }
            }
            // exp + mask + store P^T (64-bit stores of natural row pairs)
#pragma unroll
            for (int rp = 0; rp < 4; rp++) {
#pragma unroll
                for (int j = 0; j < 8; j++) {
                    float2 sv = unpk(acc1[rp][j]);
                    int c = cg + 16 * j;
                    int r = r0 + 2 * rp;
                    float p0 = sM[r * 128 + c]       ? __expf(sv.x) : 0.f;
                    float p1 = sM[(r + 1) * 128 + c] ? __expf(sv.y) : 0.f;
                    *(unsigned long long*)(sP + c * 132 + r) = pack2f(p0, p1);
                }
            }
        }
        __syncthreads();

        // ---- denominator partial sums (warps 0-3 only) ----
        if (t < 128) {
            float s0 = 0.f, s1 = 0.f, s2 = 0.f, s3 = 0.f;
#pragma unroll 4
            for (int c = 0; c < 128; c += 4) {
                s0 += sP[(c + 0) * 132 + t];
                s1 += sP[(c + 1) * 132 + t];
                s2 += sP[(c + 2) * 132 + t];
                s3 += sP[(c + 3) * 132 + t];
            }
            sDen[t] += (s0 + s1) + (s2 + s3);
        }

        // ---- stage 2: O += P @ L (each slice covers 64 k's) ----
        {
            const int kb = sl * 64;
#pragma unroll 2
            for (int kk = 0; kk < 64; kk++) {
                const int kg = kb + kk;
                const ulonglong2 pa = *(const ulonglong2*)(sP + kg * 132 + r20);
                const ulonglong2 pb = *(const ulonglong2*)(sP + kg * 132 + r20 + 4);
                const unsigned long long a0 = pa.x, a1 = pa.y, a2 = pb.x, a3 = pb.y;
#pragma unroll
                for (int j = 0; j < 8; j++) {
                    unsigned long long bb = pack2(sL[kg * 64 + cg2 + 8 * j]);
                    fma2(acc2[0][j], a0, bb);
                    fma2(acc2[1][j], a1, bb);
                    fma2(acc2[2][j], a2, bb);
                    fma2(acc2[3][j], a3, bb);
                }
            }
        }
    }

    // ---- epilogue: combine k-slices, normalize, exp, store ----
    __syncthreads();
    float* osc = sP;   // reuse, stride 68
    if (sl == 1) {
#pragma unroll
        for (int rp = 0; rp < 4; rp++) {
#pragma unroll
            for (int j = 0; j < 8; j++) {
                float2 v = unpk(acc2[rp][j]);
                int r = r20 + 2 * rp;
                int c = cg2 + 8 * j;
                osc[r * 68 + c]       = v.x;
                osc[(r + 1) * 68 + c] = v.y;
            }
        }
    }
    __syncthreads();
    if (sl == 0) {
#pragma unroll
        for (int rp = 0; rp < 4; rp++) {
#pragma unroll
            for (int j = 0; j < 8; j++) {
                float2 v = unpk(acc2[rp][j]);
                int r = r20 + 2 * rp;
                int c = cg2 + 8 * j;
                float o0 = __expf((v.x + osc[r * 68 + c]) / sDen[r]);
                float o1 = __expf((v.y + osc[(r + 1) * 68 + c]) / sDen[r + 1]);
                out[((size_t)bh * SEQ + q0 + r) * DIM + c]     = o0;
                out[((size_t)bh * SEQ + q0 + r + 1) * DIM + c] = o1;
            }
        }
    }
}

extern "C" void kernel_launch(void* const* d_in, const int* in_sizes, int n_in,
                              void* d_out, int out_size) {
    const float* Q = (const float*)d_in[0];
    const float* K = (const float*)d_in[1];
    const float* V = (const float*)d_in[2];
    const unsigned char* M = (const unsigned char*)d_in[3];
    float* out = (float*)d_out;

    // 0) detect mask element width (bool byte vs int32/float32 widened)
    mask_detect_kernel<<<1, 256>>>((const unsigned int*)M);

    // 1) L = log_sigmoid(V): BH*SEQ*DIM/4 = 2097152 float4 -> 8192 blocks x 256
    logsig_kernel<<<8192, 256>>>((const float4*)V);

    // 2) attention: grid = (q tiles, batch*heads)
    cudaFuncSetAttribute(attn_kernel,
                         cudaFuncAttributeMaxDynamicSharedMemorySize, SMEM_BYTES);
    dim3 grid(SEQ / QT, BH);
    attn_kernel<<<grid, 256, SMEM_BYTES>>>(Q, K, M, out);
}

// round 7
// speedup vs baseline: 5.4571x; 5.4497x over previous
#include <cuda_runtime.h>
#include <cuda_fp16.h>
#include <cstdint>

// ============================ problem constants ============================
#define BH   128
#define SEQ  1024
#define DIM  64
#define QT   128
#define KT   128
#define NIT  8

// ============================ device scratch ============================
__device__ __half g_Qh[BH * SEQ * DIM];   // Q * 0.125, fp16
__device__ __half g_Kh[BH * SEQ * DIM];   // K, fp16
__device__ __half g_Lh[BH * SEQ * DIM];   // log_sigmoid(V), fp16
__device__ uint4  g_Mb[8 * SEQ * 8];      // mask bits: [b][row][8 uint4 = 1024 bits]
__device__ int    g_mask_mode;

// ============================ PTX helpers ============================
__device__ __forceinline__ uint32_t smem_u32(const void* p) {
    uint32_t a;
    asm("{ .reg .u64 t; cvta.to.shared.u64 t, %1; cvt.u32.u64 %0, t; }"
        : "=r"(a) : "l"(p));
    return a;
}
__device__ __forceinline__ uint32_t swz(uint32_t o) { return o ^ ((o >> 3) & 0x70); }

__device__ __forceinline__ void ldmx4(uint32_t& r0, uint32_t& r1, uint32_t& r2,
                                      uint32_t& r3, uint32_t a) {
    asm volatile("ldmatrix.sync.aligned.m8n8.x4.shared.b16 {%0,%1,%2,%3}, [%4];"
        : "=r"(r0), "=r"(r1), "=r"(r2), "=r"(r3) : "r"(a));
}
__device__ __forceinline__ void ldmx4t(uint32_t& r0, uint32_t& r1, uint32_t& r2,
                                       uint32_t& r3, uint32_t a) {
    asm volatile("ldmatrix.sync.aligned.m8n8.x4.trans.shared.b16 {%0,%1,%2,%3}, [%4];"
        : "=r"(r0), "=r"(r1), "=r"(r2), "=r"(r3) : "r"(a));
}
__device__ __forceinline__ void mma_f16(float* c, const uint32_t* a,
                                        uint32_t b0, uint32_t b1) {
    asm volatile("mma.sync.aligned.m16n8k16.row.col.f32.f16.f16.f32 "
        "{%0,%1,%2,%3}, {%4,%5,%6,%7}, {%8,%9}, {%0,%1,%2,%3};"
        : "+f"(c[0]), "+f"(c[1]), "+f"(c[2]), "+f"(c[3])
        : "r"(a[0]), "r"(a[1]), "r"(a[2]), "r"(a[3]), "r"(b0), "r"(b1));
}
__device__ __forceinline__ uint32_t pack_h2(float lo, float hi) {
    uint32_t r;
    asm("cvt.rn.f16x2.f32 %0, %1, %2;" : "=r"(r) : "f"(hi), "f"(lo));
    return r;
}
__device__ __forceinline__ void cp16(uint32_t s, const void* g) {
    asm volatile("cp.async.cg.shared.global [%0], [%1], 16;" :: "r"(s), "l"(g));
}
#define CP_COMMIT() asm volatile("cp.async.commit_group;" ::: "memory")
#define CP_WAIT(n)  asm volatile("cp.async.wait_group %0;" :: "n"(n) : "memory")

// ============================ preprocessing ============================
__global__ void mask_detect_kernel(const unsigned int* __restrict__ m) {
    int t = threadIdx.x;
    int wide_ok = 1;
#pragma unroll
    for (int i = 0; i < 4; i++) {
        unsigned int w = m[t * 4 + i];
        if (!(w == 0u || w == 1u || w == 0x3F800000u)) wide_ok = 0;
    }
    int all_wide = __syncthreads_and(wide_ok);
    if (t == 0) g_mask_mode = all_wide ? 1 : 0;
}

// one u32 of mask bits (32 elements) per thread; 8*1024*32 = 262144 words
__global__ void prep_maskbits(const void* __restrict__ src) {
    int idx = blockIdx.x * 256 + threadIdx.x;
    unsigned w = 0;
    if (g_mask_mode == 1) {
        const uint4* s = (const uint4*)src + (size_t)idx * 8;
#pragma unroll
        for (int i = 0; i < 8; i++) {
            uint4 a = s[i];
            w |= (a.x ? 1u : 0u) << (i * 4 + 0);
            w |= (a.y ? 1u : 0u) << (i * 4 + 1);
            w |= (a.z ? 1u : 0u) << (i * 4 + 2);
            w |= (a.w ? 1u : 0u) << (i * 4 + 3);
        }
    } else {
        const uint4* s = (const uint4*)src + (size_t)idx * 2;
#pragma unroll
        for (int i = 0; i < 2; i++) {
            uint4 a = s[i];
            const unsigned* aw = (const unsigned*)&a;
#pragma unroll
            for (int bq = 0; bq < 4; bq++) {
                unsigned bw = aw[bq];
                w |= ((bw & 0x000000ffu) ? 1u : 0u) << (i * 16 + bq * 4 + 0);
                w |= ((bw & 0x0000ff00u) ? 1u : 0u) << (i * 16 + bq * 4 + 1);
                w |= ((bw & 0x00ff0000u) ? 1u : 0u) << (i * 16 + bq * 4 + 2);
                w |= ((bw & 0xff000000u) ? 1u : 0u) << (i * 16 + bq * 4 + 3);
            }
        }
    }
    ((unsigned*)g_Mb)[idx] = w;
}

// Q*0.125 -> fp16, K -> fp16, log_sigmoid(V) -> fp16
__global__ void prep_qkl(const float4* __restrict__ Q, const float4* __restrict__ K,
                         const float4* __restrict__ V) {
    int i = blockIdx.x * 256 + threadIdx.x;
    float4 q = Q[i];
    __half2* qo = (__half2*)g_Qh;
    qo[2 * i]     = __floats2half2_rn(q.x * 0.125f, q.y * 0.125f);
    qo[2 * i + 1] = __floats2half2_rn(q.z * 0.125f, q.w * 0.125f);
    float4 k = K[i];
    __half2* ko = (__half2*)g_Kh;
    ko[2 * i]     = __floats2half2_rn(k.x, k.y);
    ko[2 * i + 1] = __floats2half2_rn(k.z, k.w);
    float4 v = V[i];
    float a0 = fminf(v.x, 0.f) - log1pf(__expf(-fabsf(v.x)));
    float a1 = fminf(v.y, 0.f) - log1pf(__expf(-fabsf(v.y)));
    float a2 = fminf(v.z, 0.f) - log1pf(__expf(-fabsf(v.z)));
    float a3 = fminf(v.w, 0.f) - log1pf(__expf(-fabsf(v.w)));
    __half2* lo = (__half2*)g_Lh;
    lo[2 * i]     = __floats2half2_rn(a0, a1);
    lo[2 * i + 1] = __floats2half2_rn(a2, a3);
}

// ============================ attention kernel ============================
// smem: 2 stages x (K tile 16KB + L tile 16KB) = 64KB; rows 128B, SW128 swizzle
#define ST_K(s) ((s) * 32768)
#define ST_L(s) ((s) * 32768 + 16384)
#define SMEM_BYTES 65536

__device__ __forceinline__ void prefetch_tiles(char* smem, int st, int t,
                                               const __half* Kb, const __half* Lb,
                                               int k0, uint32_t sb) {
#pragma unroll
    for (int i = t; i < 1024; i += 256) {
        int r = i >> 3, j = i & 7;
        cp16(sb + ST_K(st) + swz(r * 128 + j * 16), Kb + (size_t)(k0 + r) * DIM + j * 8);
    }
#pragma unroll
    for (int i = t; i < 1024; i += 256) {
        int r = i >> 3, j = i & 7;
        cp16(sb + ST_L(st) + swz(r * 128 + j * 16), Lb + (size_t)(k0 + r) * DIM + j * 8);
    }
}

__global__ void __launch_bounds__(256, 1)
attn_kernel(float* __restrict__ out) {
    extern __shared__ char smem[];
    const uint32_t sb = smem_u32(smem);
    const int t = threadIdx.x, w = t >> 5, lane = t & 31;
    const int bh = blockIdx.y, q0 = blockIdx.x * QT;
    const int b = bh >> 4;

    const __half* Kbh = g_Kh + (size_t)bh * SEQ * DIM;
    const __half* Lbh = g_Lh + (size_t)bh * SEQ * DIM;

    // ---- Q tile -> smem (stage0 K area) -> A-fragments in registers ----
    {
        const __half* Qs = g_Qh + ((size_t)bh * SEQ + q0) * DIM;
#pragma unroll
        for (int i = t; i < 1024; i += 256) {
            int r = i >> 3, j = i & 7;
            cp16(sb + ST_K(0) + swz(r * 128 + j * 16), Qs + (size_t)r * DIM + j * 8);
        }
    }
    CP_COMMIT(); CP_WAIT(0);
    __syncthreads();

    const uint32_t xr = (uint32_t)(lane & 7) << 4;   // swizzle XOR (row&7)<<4
    uint32_t qf[4][4];
    {
        uint32_t base = sb + ST_K(0) + (uint32_t)(16 * w + (lane & 15)) * 128;
        uint32_t ch = (uint32_t)(lane >> 4) << 4;    // +16B for k8..15 octets
#pragma unroll
        for (int kd = 0; kd < 4; kd++)
            ldmx4(qf[kd][0], qf[kd][1], qf[kd][2], qf[kd][3],
                  base + (((uint32_t)kd * 32 + ch) ^ xr));
    }
    __syncthreads();

    // mask bit rows (uint4 = 128 bits = one KT chunk)
    const uint4* mr0 = g_Mb + ((size_t)b * SEQ + q0 + 16 * w + (lane >> 2)) * 8;
    const uint4* mr1 = mr0 + 64;                     // +8 rows

    // per-thread ldmatrix base offsets
    const uint32_t rbK = (uint32_t)((lane & 7) + ((lane >> 4) << 3));  // K B-frag rows
    const uint32_t csK = (uint32_t)(((lane >> 3) & 1) << 4);           // K col sel
    const uint32_t rbL = (uint32_t)((lane & 7) + (((lane >> 3) & 1) << 3)); // L rows
    const uint32_t csL = (uint32_t)(((lane >> 4) & 1) << 4);           // L col sel

    float oacc[8][4];
#pragma unroll
    for (int j = 0; j < 8; j++)
#pragma unroll
        for (int x = 0; x < 4; x++) oacc[j][x] = 0.f;
    float den0 = 0.f, den1 = 0.f;
    const int cb = 2 * (lane & 3);

    prefetch_tiles(smem, 0, t, Kbh, Lbh, 0, sb);
    CP_COMMIT();

    for (int it = 0; it < NIT; it++) {
        const int st = it & 1;
        if (it < NIT - 1) {
            prefetch_tiles(smem, st ^ 1, t, Kbh, Lbh, (it + 1) * KT, sb);
            CP_COMMIT();
            CP_WAIT(1);
        } else {
            CP_WAIT(0);
        }
        __syncthreads();

        uint4 m0 = mr0[it], m1 = mr1[it];

        // ---- GEMM1: S[16x128] = Q @ K^T ----
        float c[16][4];
#pragma unroll
        for (int j = 0; j < 16; j++)
#pragma unroll
            for (int x = 0; x < 4; x++) c[j][x] = 0.f;

        const uint32_t baseK = sb + ST_K(st) + rbK * 128;
#pragma unroll
        for (int jp = 0; jp < 8; jp++) {
            uint32_t bfr[4][4];
#pragma unroll
            for (int kd = 0; kd < 4; kd++)
                ldmx4(bfr[kd][0], bfr[kd][1], bfr[kd][2], bfr[kd][3],
                      baseK + (uint32_t)jp * 2048 + (((uint32_t)kd * 32 + csK) ^ xr));
#pragma unroll
            for (int kd = 0; kd < 4; kd++) {
                mma_f16(c[2 * jp],     qf[kd], bfr[kd][0], bfr[kd][1]);
                mma_f16(c[2 * jp + 1], qf[kd], bfr[kd][2], bfr[kd][3]);
            }
        }

        // ---- epilogue: P = mask * exp(S) in registers (C-frag == A-frag layout) ----
        uint32_t p2[16][2];
#pragma unroll
        for (int j = 0; j < 16; j++) {
            const unsigned* w0 = (const unsigned*)&m0;
            const unsigned* w1 = (const unsigned*)&m1;
            unsigned bits0 = w0[j >> 2] >> (((8 * j) & 31) + cb);
            unsigned bits1 = w1[j >> 2] >> (((8 * j) & 31) + cb);
            float e0 = (bits0 & 1u) ? __expf(c[j][0]) : 0.f;
            float e1 = (bits0 & 2u) ? __expf(c[j][1]) : 0.f;
            float e2 = (bits1 & 1u) ? __expf(c[j][2]) : 0.f;
            float e3 = (bits1 & 2u) ? __expf(c[j][3]) : 0.f;
            den0 += e0 + e1;
            den1 += e2 + e3;
            p2[j][0] = pack_h2(e0, e1);
            p2[j][1] = pack_h2(e2, e3);
        }

        // ---- GEMM2: O[16x64] += P @ L ----
        const uint32_t baseL = sb + ST_L(st) + rbL * 128;
#pragma unroll
        for (int kk = 0; kk < 8; kk++) {
            uint32_t a[4] = {p2[2 * kk][0], p2[2 * kk][1],
                             p2[2 * kk + 1][0], p2[2 * kk + 1][1]};
#pragma unroll
            for (int dp = 0; dp < 4; dp++) {
                uint32_t b0, b1, b2, b3;
                ldmx4t(b0, b1, b2, b3,
                       baseL + (uint32_t)kk * 2048 + (((uint32_t)dp * 32 + csL) ^ xr));
                mma_f16(oacc[2 * dp],     a, b0, b1);
                mma_f16(oacc[2 * dp + 1], a, b2, b3);
            }
        }
        __syncthreads();
    }

    // ---- final: quad-reduce den, normalize, exp, store ----
    den0 += __shfl_xor_sync(0xffffffffu, den0, 1);
    den0 += __shfl_xor_sync(0xffffffffu, den0, 2);
    den1 += __shfl_xor_sync(0xffffffffu, den1, 1);
    den1 += __shfl_xor_sync(0xffffffffu, den1, 2);
    const float inv0 = 1.f / den0, inv1 = 1.f / den1;

    const int r0 = q0 + 16 * w + (lane >> 2);
    float* o0 = out + ((size_t)bh * SEQ + r0) * DIM + cb;
    float* o1 = o0 + 8 * DIM;
#pragma unroll
    for (int j = 0; j < 8; j++) {
        float2 v0, v1;
        v0.x = __expf(oacc[j][0] * inv0);
        v0.y = __expf(oacc[j][1] * inv0);
        v1.x = __expf(oacc[j][2] * inv1);
        v1.y = __expf(oacc[j][3] * inv1);
        *(float2*)(o0 + 8 * j) = v0;
        *(float2*)(o1 + 8 * j) = v1;
    }
}

// ============================ launch ============================
extern "C" void kernel_launch(void* const* d_in, const int* in_sizes, int n_in,
                              void* d_out, int out_size) {
    const float* Q = (const float*)d_in[0];
    const float* K = (const float*)d_in[1];
    const float* V = (const float*)d_in[2];
    const void*  M = d_in[3];
    float* out = (float*)d_out;

    mask_detect_kernel<<<1, 256>>>((const unsigned int*)M);
    prep_maskbits<<<1024, 256>>>(M);
    prep_qkl<<<8192, 256>>>((const float4*)Q, (const float4*)K, (const float4*)V);

    cudaFuncSetAttribute(attn_kernel,
                         cudaFuncAttributeMaxDynamicSharedMemorySize, SMEM_BYTES);
    dim3 grid(SEQ / QT, BH);
    attn_kernel<<<grid, 256, SMEM_BYTES>>>(out);
}

// round 8
// speedup vs baseline: 5.8313x; 1.0686x over previous
#include <cuda_runtime.h>
#include <cuda_fp16.h>
#include <cstdint>

// ============================ problem constants ============================
#define BH   128
#define SEQ  1024
#define DIM  64
#define QT   64          // q rows per CTA (4 warps x 16 rows)
#define KT   128
#define NIT  8
#define NTHR 128

// ============================ device scratch ============================
__device__ __half g_Qh[BH * SEQ * DIM];   // Q * 0.125, fp16
__device__ __half g_Kh[BH * SEQ * DIM];   // K, fp16
__device__ __half g_Lh[BH * SEQ * DIM];   // log_sigmoid(V), fp16
__device__ uint4  g_Mb[8 * SEQ * 8];      // mask bits: [b][row][8 uint4 = 1024 bits]
__device__ int    g_mask_mode;

// ============================ PTX helpers ============================
__device__ __forceinline__ uint32_t smem_u32(const void* p) {
    uint32_t a;
    asm("{ .reg .u64 t; cvta.to.shared.u64 t, %1; cvt.u32.u64 %0, t; }"
        : "=r"(a) : "l"(p));
    return a;
}
__device__ __forceinline__ uint32_t swz(uint32_t o) { return o ^ ((o >> 3) & 0x70); }

__device__ __forceinline__ void ldmx4(uint32_t& r0, uint32_t& r1, uint32_t& r2,
                                      uint32_t& r3, uint32_t a) {
    asm volatile("ldmatrix.sync.aligned.m8n8.x4.shared.b16 {%0,%1,%2,%3}, [%4];"
        : "=r"(r0), "=r"(r1), "=r"(r2), "=r"(r3) : "r"(a));
}
__device__ __forceinline__ void ldmx4t(uint32_t& r0, uint32_t& r1, uint32_t& r2,
                                       uint32_t& r3, uint32_t a) {
    asm volatile("ldmatrix.sync.aligned.m8n8.x4.trans.shared.b16 {%0,%1,%2,%3}, [%4];"
        : "=r"(r0), "=r"(r1), "=r"(r2), "=r"(r3) : "r"(a));
}
__device__ __forceinline__ void mma_f16(float* c, const uint32_t* a,
                                        uint32_t b0, uint32_t b1) {
    asm volatile("mma.sync.aligned.m16n8k16.row.col.f32.f16.f16.f32 "
        "{%0,%1,%2,%3}, {%4,%5,%6,%7}, {%8,%9}, {%0,%1,%2,%3};"
        : "+f"(c[0]), "+f"(c[1]), "+f"(c[2]), "+f"(c[3])
        : "r"(a[0]), "r"(a[1]), "r"(a[2]), "r"(a[3]), "r"(b0), "r"(b1));
}
__device__ __forceinline__ uint32_t pack_h2(float lo, float hi) {
    uint32_t r;
    asm("cvt.rn.f16x2.f32 %0, %1, %2;" : "=r"(r) : "f"(hi), "f"(lo));
    return r;
}
__device__ __forceinline__ void cp16(uint32_t s, const void* g) {
    asm volatile("cp.async.cg.shared.global [%0], [%1], 16;" :: "r"(s), "l"(g));
}
#define CP_COMMIT() asm volatile("cp.async.commit_group;" ::: "memory")
#define CP_WAIT(n)  asm volatile("cp.async.wait_group %0;" :: "n"(n) : "memory")

// ============================ preprocessing ============================
__global__ void mask_detect_kernel(const unsigned int* __restrict__ m) {
    int t = threadIdx.x;
    int wide_ok = 1;
#pragma unroll
    for (int i = 0; i < 4; i++) {
        unsigned int w = m[t * 4 + i];
        if (!(w == 0u || w == 1u || w == 0x3F800000u)) wide_ok = 0;
    }
    int all_wide = __syncthreads_and(wide_ok);
    if (t == 0) g_mask_mode = all_wide ? 1 : 0;
}

// one u32 of mask bits (32 elements) per thread; 262144 words
__global__ void prep_maskbits(const void* __restrict__ src) {
    int idx = blockIdx.x * 256 + threadIdx.x;
    unsigned w = 0;
    if (g_mask_mode == 1) {
        const uint4* s = (const uint4*)src + (size_t)idx * 8;
#pragma unroll
        for (int i = 0; i < 8; i++) {
            uint4 a = s[i];
            w |= (a.x ? 1u : 0u) << (i * 4 + 0);
            w |= (a.y ? 1u : 0u) << (i * 4 + 1);
            w |= (a.z ? 1u : 0u) << (i * 4 + 2);
            w |= (a.w ? 1u : 0u) << (i * 4 + 3);
        }
    } else {
        const uint4* s = (const uint4*)src + (size_t)idx * 2;
#pragma unroll
        for (int i = 0; i < 2; i++) {
            uint4 a = s[i];
            const unsigned* aw = (const unsigned*)&a;
#pragma unroll
            for (int bq = 0; bq < 4; bq++) {
                unsigned bw = aw[bq];
                w |= ((bw & 0x000000ffu) ? 1u : 0u) << (i * 16 + bq * 4 + 0);
                w |= ((bw & 0x0000ff00u) ? 1u : 0u) << (i * 16 + bq * 4 + 1);
                w |= ((bw & 0x00ff0000u) ? 1u : 0u) << (i * 16 + bq * 4 + 2);
                w |= ((bw & 0xff000000u) ? 1u : 0u) << (i * 16 + bq * 4 + 3);
            }
        }
    }
    ((unsigned*)g_Mb)[idx] = w;
}

// Q*0.125 -> fp16, K -> fp16, log_sigmoid(V) -> fp16
__global__ void prep_qkl(const float4* __restrict__ Q, const float4* __restrict__ K,
                         const float4* __restrict__ V) {
    int i = blockIdx.x * 256 + threadIdx.x;
    float4 q = Q[i];
    __half2* qo = (__half2*)g_Qh;
    qo[2 * i]     = __floats2half2_rn(q.x * 0.125f, q.y * 0.125f);
    qo[2 * i + 1] = __floats2half2_rn(q.z * 0.125f, q.w * 0.125f);
    float4 k = K[i];
    __half2* ko = (__half2*)g_Kh;
    ko[2 * i]     = __floats2half2_rn(k.x, k.y);
    ko[2 * i + 1] = __floats2half2_rn(k.z, k.w);
    float4 v = V[i];
    float a0 = fminf(v.x, 0.f) - log1pf(__expf(-fabsf(v.x)));
    float a1 = fminf(v.y, 0.f) - log1pf(__expf(-fabsf(v.y)));
    float a2 = fminf(v.z, 0.f) - log1pf(__expf(-fabsf(v.z)));
    float a3 = fminf(v.w, 0.f) - log1pf(__expf(-fabsf(v.w)));
    __half2* lo = (__half2*)g_Lh;
    lo[2 * i]     = __floats2half2_rn(a0, a1);
    lo[2 * i + 1] = __floats2half2_rn(a2, a3);
}

// ============================ attention kernel ============================
// smem: 2 stages x (K tile 16KB + L tile 16KB) = 64KB; rows 128B, SW128 swizzle
#define ST_K(s) ((s) * 32768)
#define ST_L(s) ((s) * 32768 + 16384)
#define SMEM_BYTES 65536

__device__ __forceinline__ void prefetch_tiles(int st, int t,
                                               const __half* Kb, const __half* Lb,
                                               int k0, uint32_t sb) {
#pragma unroll
    for (int i = t; i < 1024; i += NTHR) {
        int r = i >> 3, j = i & 7;
        cp16(sb + ST_K(st) + swz(r * 128 + j * 16), Kb + (size_t)(k0 + r) * DIM + j * 8);
    }
#pragma unroll
    for (int i = t; i < 1024; i += NTHR) {
        int r = i >> 3, j = i & 7;
        cp16(sb + ST_L(st) + swz(r * 128 + j * 16), Lb + (size_t)(k0 + r) * DIM + j * 8);
    }
}

__global__ void __launch_bounds__(NTHR, 2)
attn_kernel(float* __restrict__ out) {
    extern __shared__ char smem[];
    const uint32_t sb = smem_u32(smem);
    const int t = threadIdx.x, w = t >> 5, lane = t & 31;
    const int bh = blockIdx.y, q0 = blockIdx.x * QT;
    const int b = bh >> 4;

    const __half* Kbh = g_Kh + (size_t)bh * SEQ * DIM;
    const __half* Lbh = g_Lh + (size_t)bh * SEQ * DIM;

    // ---- Q tile (64 rows) -> smem (stage0 K area) -> A-fragments ----
    {
        const __half* Qs = g_Qh + ((size_t)bh * SEQ + q0) * DIM;
#pragma unroll
        for (int i = t; i < 512; i += NTHR) {
            int r = i >> 3, j = i & 7;
            cp16(sb + ST_K(0) + swz(r * 128 + j * 16), Qs + (size_t)r * DIM + j * 8);
        }
    }
    CP_COMMIT(); CP_WAIT(0);
    __syncthreads();

    const uint32_t xr = (uint32_t)(lane & 7) << 4;   // swizzle XOR (row&7)<<4
    uint32_t qf[4][4];
    {
        uint32_t base = sb + ST_K(0) + (uint32_t)(16 * w + (lane & 15)) * 128;
        uint32_t ch = (uint32_t)(lane >> 4) << 4;    // +16B for k8..15 octets
#pragma unroll
        for (int kd = 0; kd < 4; kd++)
            ldmx4(qf[kd][0], qf[kd][1], qf[kd][2], qf[kd][3],
                  base + (((uint32_t)kd * 32 + ch) ^ xr));
    }
    __syncthreads();

    // mask bit rows (uint4 = 128 bits = one KT chunk)
    const uint4* mr0 = g_Mb + ((size_t)b * SEQ + q0 + 16 * w + (lane >> 2)) * 8;
    const uint4* mr1 = mr0 + 64;                     // +8 rows

    // per-thread ldmatrix base offsets
    const uint32_t rbK = (uint32_t)((lane & 7) + ((lane >> 4) << 3));  // K B-frag rows
    const uint32_t csK = (uint32_t)(((lane >> 3) & 1) << 4);           // K col sel
    const uint32_t rbL = (uint32_t)((lane & 7) + (((lane >> 3) & 1) << 3)); // L rows
    const uint32_t csL = (uint32_t)(((lane >> 4) & 1) << 4);           // L col sel

    float oacc[8][4];
#pragma unroll
    for (int j = 0; j < 8; j++)
#pragma unroll
        for (int x = 0; x < 4; x++) oacc[j][x] = 0.f;
    float den0 = 0.f, den1 = 0.f;
    const int cb = 2 * (lane & 3);

    prefetch_tiles(0, t, Kbh, Lbh, 0, sb);
    CP_COMMIT();

    for (int it = 0; it < NIT; it++) {
        const int st = it & 1;
        if (it < NIT - 1) {
            prefetch_tiles(st ^ 1, t, Kbh, Lbh, (it + 1) * KT, sb);
            CP_COMMIT();
            CP_WAIT(1);
        } else {
            CP_WAIT(0);
        }
        __syncthreads();

        uint4 m0 = mr0[it], m1 = mr1[it];

        // ---- GEMM1: S[16x128] = Q @ K^T ----
        float c[16][4];
#pragma unroll
        for (int j = 0; j < 16; j++)
#pragma unroll
            for (int x = 0; x < 4; x++) c[j][x] = 0.f;

        const uint32_t baseK = sb + ST_K(st) + rbK * 128;
#pragma unroll
        for (int jp = 0; jp < 8; jp++) {
            uint32_t bfr[4][4];
#pragma unroll
            for (int kd = 0; kd < 4; kd++)
                ldmx4(bfr[kd][0], bfr[kd][1], bfr[kd][2], bfr[kd][3],
                      baseK + (uint32_t)jp * 2048 + (((uint32_t)kd * 32 + csK) ^ xr));
#pragma unroll
            for (int kd = 0; kd < 4; kd++) {
                mma_f16(c[2 * jp],     qf[kd], bfr[kd][0], bfr[kd][1]);
                mma_f16(c[2 * jp + 1], qf[kd], bfr[kd][2], bfr[kd][3]);
            }
        }

        // ---- epilogue: P = mask * exp(S) in registers (C-frag == A-frag layout) ----
        uint32_t p2[16][2];
#pragma unroll
        for (int j = 0; j < 16; j++) {
            const unsigned* w0 = (const unsigned*)&m0;
            const unsigned* w1 = (const unsigned*)&m1;
            unsigned bits0 = w0[j >> 2] >> (((8 * j) & 31) + cb);
            unsigned bits1 = w1[j >> 2] >> (((8 * j) & 31) + cb);
            float e0 = (bits0 & 1u) ? __expf(c[j][0]) : 0.f;
            float e1 = (bits0 & 2u) ? __expf(c[j][1]) : 0.f;
            float e2 = (bits1 & 1u) ? __expf(c[j][2]) : 0.f;
            float e3 = (bits1 & 2u) ? __expf(c[j][3]) : 0.f;
            den0 += e0 + e1;
            den1 += e2 + e3;
            p2[j][0] = pack_h2(e0, e1);
            p2[j][1] = pack_h2(e2, e3);
        }

        // ---- GEMM2: O[16x64] += P @ L ----
        const uint32_t baseL = sb + ST_L(st) + rbL * 128;
#pragma unroll
        for (int kk = 0; kk < 8; kk++) {
            uint32_t a[4] = {p2[2 * kk][0], p2[2 * kk][1],
                             p2[2 * kk + 1][0], p2[2 * kk + 1][1]};
#pragma unroll
            for (int dp = 0; dp < 4; dp++) {
                uint32_t b0, b1, b2, b3;
                ldmx4t(b0, b1, b2, b3,
                       baseL + (uint32_t)kk * 2048 + (((uint32_t)dp * 32 + csL) ^ xr));
                mma_f16(oacc[2 * dp],     a, b0, b1);
                mma_f16(oacc[2 * dp + 1], a, b2, b3);
            }
        }
        __syncthreads();
    }

    // ---- final: quad-reduce den, normalize, exp, store ----
    den0 += __shfl_xor_sync(0xffffffffu, den0, 1);
    den0 += __shfl_xor_sync(0xffffffffu, den0, 2);
    den1 += __shfl_xor_sync(0xffffffffu, den1, 1);
    den1 += __shfl_xor_sync(0xffffffffu, den1, 2);
    const float inv0 = 1.f / den0, inv1 = 1.f / den1;

    const int r0 = q0 + 16 * w + (lane >> 2);
    float* o0 = out + ((size_t)bh * SEQ + r0) * DIM + cb;
    float* o1 = o0 + 8 * DIM;
#pragma unroll
    for (int j = 0; j < 8; j++) {
        float2 v0, v1;
        v0.x = __expf(oacc[j][0] * inv0);
        v0.y = __expf(oacc[j][1] * inv0);
        v1.x = __expf(oacc[j][2] * inv1);
        v1.y = __expf(oacc[j][3] * inv1);
        *(float2*)(o0 + 8 * j) = v0;
        *(float2*)(o1 + 8 * j) = v1;
    }
}

// ============================ launch ============================
extern "C" void kernel_launch(void* const* d_in, const int* in_sizes, int n_in,
                              void* d_out, int out_size) {
    const float* Q = (const float*)d_in[0];
    const float* K = (const float*)d_in[1];
    const float* V = (const float*)d_in[2];
    const void*  M = d_in[3];
    float* out = (float*)d_out;

    mask_detect_kernel<<<1, 256>>>((const unsigned int*)M);
    prep_maskbits<<<1024, 256>>>(M);
    prep_qkl<<<8192, 256>>>((const float4*)Q, (const float4*)K, (const float4*)V);

    cudaFuncSetAttribute(attn_kernel,
                         cudaFuncAttributeMaxDynamicSharedMemorySize, SMEM_BYTES);
    dim3 grid(SEQ / QT, BH);
    attn_kernel<<<grid, NTHR, SMEM_BYTES>>>(out);
}

// round 9
// speedup vs baseline: 7.5296x; 1.2912x over previous
#include <cuda_runtime.h>
#include <cuda_fp16.h>
#include <cstdint>

// ============================ problem constants ============================
#define BH   128
#define SEQ  1024
#define DIM  64
#define QT   64          // q rows per CTA (4 warps x 16 rows)
#define KT   128
#define NIT  8
#define NTHR 128
// fold 1/sqrt(64) * log2(e) into Q so scores are in log2 domain
#define QSCALE 0.1803368801111244f

// ============================ device scratch ============================
__device__ __half g_Kh[BH * SEQ * DIM];   // K, fp16
__device__ __half g_Lh[BH * SEQ * DIM];   // log_sigmoid(V), fp16
// permuted mask bits: [b][row][it][quad] u32; bit(2i+z) = mask[b][row][it*128 + i*8 + 2*quad + z]
__device__ unsigned g_Mp[8 * SEQ * NIT * 4];

// ============================ PTX helpers ============================
__device__ __forceinline__ uint32_t smem_u32(const void* p) {
    uint32_t a;
    asm("{ .reg .u64 t; cvta.to.shared.u64 t, %1; cvt.u32.u64 %0, t; }"
        : "=r"(a) : "l"(p));
    return a;
}
__device__ __forceinline__ uint32_t swz(uint32_t o) { return o ^ ((o >> 3) & 0x70); }

__device__ __forceinline__ void ldmx4(uint32_t& r0, uint32_t& r1, uint32_t& r2,
                                      uint32_t& r3, uint32_t a) {
    asm volatile("ldmatrix.sync.aligned.m8n8.x4.shared.b16 {%0,%1,%2,%3}, [%4];"
        : "=r"(r0), "=r"(r1), "=r"(r2), "=r"(r3) : "r"(a));
}
__device__ __forceinline__ void ldmx4t(uint32_t& r0, uint32_t& r1, uint32_t& r2,
                                       uint32_t& r3, uint32_t a) {
    asm volatile("ldmatrix.sync.aligned.m8n8.x4.trans.shared.b16 {%0,%1,%2,%3}, [%4];"
        : "=r"(r0), "=r"(r1), "=r"(r2), "=r"(r3) : "r"(a));
}
__device__ __forceinline__ void mma_f16(float* c, const uint32_t* a,
                                        uint32_t b0, uint32_t b1) {
    asm volatile("mma.sync.aligned.m16n8k16.row.col.f32.f16.f16.f32 "
        "{%0,%1,%2,%3}, {%4,%5,%6,%7}, {%8,%9}, {%0,%1,%2,%3};"
        : "+f"(c[0]), "+f"(c[1]), "+f"(c[2]), "+f"(c[3])
        : "r"(a[0]), "r"(a[1]), "r"(a[2]), "r"(a[3]), "r"(b0), "r"(b1));
}
__device__ __forceinline__ uint32_t pack_h2(float lo, float hi) {
    uint32_t r;
    asm("cvt.rn.f16x2.f32 %0, %1, %2;" : "=r"(r) : "f"(hi), "f"(lo));
    return r;
}
__device__ __forceinline__ void cp16(uint32_t s, const void* g) {
    asm volatile("cp.async.cg.shared.global [%0], [%1], 16;" :: "r"(s), "l"(g));
}
#define CP_COMMIT() asm volatile("cp.async.commit_group;" ::: "memory")
#define CP_WAIT(n)  asm volatile("cp.async.wait_group %0;" :: "n"(n) : "memory")

// ============================ preprocessing ============================
// One thread per 128-col mask chunk; emits 4 permuted words (quad 0..3).
// Mask dtype detected inline by block-wide vote on each thread's first uint4
// (valid for both dtypes: region is within the smaller possible buffer).
__global__ void prep_maskbits(const void* __restrict__ src) {
    int idx = blockIdx.x * 256 + threadIdx.x;     // 65536 chunks
    int it = idx & 7, row = (idx >> 3) & 1023, b = idx >> 13;
    size_t cbase = (size_t)(b * 1024 + row) * 1024 + it * 128;  // elem index of chunk
    const uint4* s0 = (const uint4*)src + cbase / 16;           // byte interpretation
    uint4 d = s0[0];
    int ok = (d.x==0u||d.x==1u||d.x==0x3F800000u) && (d.y==0u||d.y==1u||d.y==0x3F800000u)
          && (d.z==0u||d.z==1u||d.z==0x3F800000u) && (d.w==0u||d.w==1u||d.w==0x3F800000u);
    int wide = __syncthreads_and(ok);
    unsigned w0 = 0, w1 = 0, w2 = 0, w3 = 0;
    if (wide) {
        const uint4* s = (const uint4*)src + cbase / 4;         // word interpretation
#pragma unroll
        for (int i = 0; i < 16; i++) {
            uint4 a = s[i * 2], c = s[i * 2 + 1];
            w0 |= ((a.x?1u:0u) << (2*i)) | ((a.y?1u:0u) << (2*i+1));
            w1 |= ((a.z?1u:0u) << (2*i)) | ((a.w?1u:0u) << (2*i+1));
            w2 |= ((c.x?1u:0u) << (2*i)) | ((c.y?1u:0u) << (2*i+1));
            w3 |= ((c.z?1u:0u) << (2*i)) | ((c.w?1u:0u) << (2*i+1));
        }
    } else {
#pragma unroll
        for (int g = 0; g < 8; g++) {
            uint4 a = s0[g];
            const unsigned* aw = (const unsigned*)&a;
#pragma unroll
            for (int h = 0; h < 2; h++) {
                int i = 2 * g + h;
                unsigned lw = aw[2 * h], hw = aw[2 * h + 1];
                w0 |= ((lw & 0x000000ffu)?1u:0u) << (2*i);
                w0 |= ((lw & 0x0000ff00u)?1u:0u) << (2*i+1);
                w1 |= ((lw & 0x00ff0000u)?1u:0u) << (2*i);
                w1 |= ((lw & 0xff000000u)?1u:0u) << (2*i+1);
                w2 |= ((hw & 0x000000ffu)?1u:0u) << (2*i);
                w2 |= ((hw & 0x0000ff00u)?1u:0u) << (2*i+1);
                w3 |= ((hw & 0x00ff0000u)?1u:0u) << (2*i);
                w3 |= ((hw & 0xff000000u)?1u:0u) << (2*i+1);
            }
        }
    }
    ((uint4*)g_Mp)[idx] = make_uint4(w0, w1, w2, w3);
}

// K -> fp16, log_sigmoid(V) -> fp16
__global__ void prep_kl(const float4* __restrict__ K, const float4* __restrict__ V) {
    int i = blockIdx.x * 256 + threadIdx.x;
    float4 k = K[i];
    __half2* ko = (__half2*)g_Kh;
    ko[2 * i]     = __floats2half2_rn(k.x, k.y);
    ko[2 * i + 1] = __floats2half2_rn(k.z, k.w);
    float4 v = V[i];
    float a0 = fminf(v.x, 0.f) - log1pf(__expf(-fabsf(v.x)));
    float a1 = fminf(v.y, 0.f) - log1pf(__expf(-fabsf(v.y)));
    float a2 = fminf(v.z, 0.f) - log1pf(__expf(-fabsf(v.z)));
    float a3 = fminf(v.w, 0.f) - log1pf(__expf(-fabsf(v.w)));
    __half2* lo = (__half2*)g_Lh;
    lo[2 * i]     = __floats2half2_rn(a0, a1);
    lo[2 * i + 1] = __floats2half2_rn(a2, a3);
}

// ============================ attention kernel ============================
// smem: 2 stages x (K tile 16KB + L tile 16KB) = 64KB; rows 128B, SW128 swizzle
#define ST_K(s) ((s) * 32768)
#define ST_L(s) ((s) * 32768 + 16384)
#define SMEM_BYTES 65536

__device__ __forceinline__ void prefetch_tiles(int st, int t,
                                               const __half* Kb, const __half* Lb,
                                               int k0, uint32_t sb) {
#pragma unroll
    for (int i = t; i < 1024; i += NTHR) {
        int r = i >> 3, j = i & 7;
        cp16(sb + ST_K(st) + swz(r * 128 + j * 16), Kb + (size_t)(k0 + r) * DIM + j * 8);
    }
#pragma unroll
    for (int i = t; i < 1024; i += NTHR) {
        int r = i >> 3, j = i & 7;
        cp16(sb + ST_L(st) + swz(r * 128 + j * 16), Lb + (size_t)(k0 + r) * DIM + j * 8);
    }
}

__global__ void __launch_bounds__(NTHR, 3)
attn_kernel(const float* __restrict__ Q, float* __restrict__ out) {
    extern __shared__ char smem[];
    const uint32_t sb = smem_u32(smem);
    const int t = threadIdx.x, w = t >> 5, lane = t & 31;
    const int bh = blockIdx.y, q0 = blockIdx.x * QT;
    const int b = bh >> 4;

    const __half* Kbh = g_Kh + (size_t)bh * SEQ * DIM;
    const __half* Lbh = g_Lh + (size_t)bh * SEQ * DIM;

    // ---- Q tile: fp32 LDG -> fp16 convert (fold scale*log2e) -> smem stage0 ----
    {
        const float4* Qs = (const float4*)(Q + ((size_t)bh * SEQ + q0) * DIM);
#pragma unroll
        for (int i = t; i < 1024; i += NTHR) {   // 64 rows x 16 float4
            int r = i >> 4, j = i & 15;
            float4 q = Qs[i];
            uint2 hv;
            hv.x = pack_h2(q.x * QSCALE, q.y * QSCALE);
            hv.y = pack_h2(q.z * QSCALE, q.w * QSCALE);
            *(uint2*)(smem + ST_K(0) + swz(r * 128 + j * 8)) = hv;
        }
    }
    __syncthreads();

    const uint32_t xr = (uint32_t)(lane & 7) << 4;   // swizzle XOR (row&7)<<4
    uint32_t qf[4][4];
    {
        uint32_t base = sb + ST_K(0) + (uint32_t)(16 * w + (lane & 15)) * 128;
        uint32_t ch = (uint32_t)(lane >> 4) << 4;    // +16B for k8..15 octets
#pragma unroll
        for (int kd = 0; kd < 4; kd++)
            ldmx4(qf[kd][0], qf[kd][1], qf[kd][2], qf[kd][3],
                  base + (((uint32_t)kd * 32 + ch) ^ xr));
    }
    __syncthreads();

    // permuted mask words: one u32 per (row, it); this thread's quad = lane&3
    const unsigned* mp0 = g_Mp + ((size_t)(b * 1024 + q0 + 16 * w + (lane >> 2)) * NIT) * 4 + (lane & 3);
    const unsigned* mp1 = mp0 + 8 * NIT * 4;         // +8 rows

    // per-thread ldmatrix base offsets
    const uint32_t rbK = (uint32_t)((lane & 7) + ((lane >> 4) << 3));       // K B-frag rows
    const uint32_t csK = (uint32_t)(((lane >> 3) & 1) << 4);                // K col sel
    const uint32_t rbL = (uint32_t)((lane & 7) + (((lane >> 3) & 1) << 3)); // L rows
    const uint32_t csL = (uint32_t)(((lane >> 4) & 1) << 4);                // L col sel

    float oacc[8][4];
#pragma unroll
    for (int j = 0; j < 8; j++)
#pragma unroll
        for (int x = 0; x < 4; x++) oacc[j][x] = 0.f;
    float den0 = 0.f, den1 = 0.f;

    prefetch_tiles(0, t, Kbh, Lbh, 0, sb);
    CP_COMMIT();

    for (int it = 0; it < NIT; it++) {
        const int st = it & 1;
        if (it < NIT - 1) {
            prefetch_tiles(st ^ 1, t, Kbh, Lbh, (it + 1) * KT, sb);
            CP_COMMIT();
            CP_WAIT(1);
        } else {
            CP_WAIT(0);
        }
        __syncthreads();

        const unsigned mw0 = mp0[it * 4], mw1 = mp1[it * 4];
        const uint32_t baseK = sb + ST_K(st) + rbK * 128;
        const uint32_t baseL = sb + ST_L(st) + rbL * 128;

#pragma unroll
        for (int h = 0; h < 2; h++) {            // two 64-col halves
            // ---- GEMM1 half: S[16x64] = Q @ K^T ----
            float c[8][4];
#pragma unroll
            for (int j = 0; j < 8; j++)
#pragma unroll
                for (int x = 0; x < 4; x++) c[j][x] = 0.f;
#pragma unroll
            for (int jp = 0; jp < 4; jp++) {
                const uint32_t ko = (uint32_t)(h * 4 + jp) * 2048;
                uint32_t bfr[4][4];
#pragma unroll
                for (int kd = 0; kd < 4; kd++)
                    ldmx4(bfr[kd][0], bfr[kd][1], bfr[kd][2], bfr[kd][3],
                          baseK + ko + (((uint32_t)kd * 32 + csK) ^ xr));
#pragma unroll
                for (int kd = 0; kd < 4; kd++) {
                    mma_f16(c[2 * jp],     qf[kd], bfr[kd][0], bfr[kd][1]);
                    mma_f16(c[2 * jp + 1], qf[kd], bfr[kd][2], bfr[kd][3]);
                }
            }

            // ---- epilogue half: P = mask * 2^S (scores already in log2 domain) ----
            const unsigned ma = mw0 >> (16 * h), mb = mw1 >> (16 * h);
            uint32_t p2[8][2];
#pragma unroll
            for (int j = 0; j < 8; j++) {
                unsigned ba = ma >> (2 * j), bb = mb >> (2 * j);
                float s0 = (ba & 1u) ? c[j][0] : -127.f;
                float s1 = (ba & 2u) ? c[j][1] : -127.f;
                float s2 = (bb & 1u) ? c[j][2] : -127.f;
                float s3 = (bb & 2u) ? c[j][3] : -127.f;
                float e0 = exp2f(s0), e1 = exp2f(s1);
                float e2 = exp2f(s2), e3 = exp2f(s3);
                den0 += e0 + e1;
                den1 += e2 + e3;
                p2[j][0] = pack_h2(e0, e1);
                p2[j][1] = pack_h2(e2, e3);
            }

            // ---- GEMM2 half: O[16x64] += P @ L (k rows h*64..h*64+63) ----
#pragma unroll
            for (int kk = 0; kk < 4; kk++) {
                const uint32_t ko = (uint32_t)(h * 4 + kk) * 2048;
                uint32_t a[4] = {p2[2 * kk][0], p2[2 * kk][1],
                                 p2[2 * kk + 1][0], p2[2 * kk + 1][1]};
#pragma unroll
                for (int dp = 0; dp < 4; dp++) {
                    uint32_t b0, b1, b2, b3;
                    ldmx4t(b0, b1, b2, b3,
                           baseL + ko + (((uint32_t)dp * 32 + csL) ^ xr));
                    mma_f16(oacc[2 * dp],     a, b0, b1);
                    mma_f16(oacc[2 * dp + 1], a, b2, b3);
                }
            }
        }
        __syncthreads();
    }

    // ---- final: quad-reduce den, normalize, exp, store ----
    den0 += __shfl_xor_sync(0xffffffffu, den0, 1);
    den0 += __shfl_xor_sync(0xffffffffu, den0, 2);
    den1 += __shfl_xor_sync(0xffffffffu, den1, 1);
    den1 += __shfl_xor_sync(0xffffffffu, den1, 2);
    const float inv0 = 1.f / den0, inv1 = 1.f / den1;

    const int cb = 2 * (lane & 3);
    const int r0 = q0 + 16 * w + (lane >> 2);
    float* o0 = out + ((size_t)bh * SEQ + r0) * DIM + cb;
    float* o1 = o0 + 8 * DIM;
#pragma unroll
    for (int j = 0; j < 8; j++) {
        float2 v0, v1;
        v0.x = __expf(oacc[j][0] * inv0);
        v0.y = __expf(oacc[j][1] * inv0);
        v1.x = __expf(oacc[j][2] * inv1);
        v1.y = __expf(oacc[j][3] * inv1);
        *(float2*)(o0 + 8 * j) = v0;
        *(float2*)(o1 + 8 * j) = v1;
    }
}

// ============================ launch ============================
extern "C" void kernel_launch(void* const* d_in, const int* in_sizes, int n_in,
                              void* d_out, int out_size) {
    const float* Q = (const float*)d_in[0];
    const float* K = (const float*)d_in[1];
    const float* V = (const float*)d_in[2];
    const void*  M = d_in[3];
    float* out = (float*)d_out;

    prep_maskbits<<<256, 256>>>(M);
    prep_kl<<<8192, 256>>>((const float4*)K, (const float4*)V);

    cudaFuncSetAttribute(attn_kernel,
                         cudaFuncAttributeMaxDynamicSharedMemorySize, SMEM_BYTES);
    dim3 grid(SEQ / QT, BH);
    attn_kernel<<<grid, NTHR, SMEM_BYTES>>>(Q, out);
}

// round 10
// speedup vs baseline: 8.3788x; 1.1128x over previous
#include <cuda_runtime.h>
#include <cuda_fp16.h>
#include <cstdint>

// ============================ problem constants ============================
#define BH   128
#define SEQ  1024
#define DIM  64
#define QT   64          // q rows per CTA (4 warps x 16 rows)
#define KT   128
#define NIT  8
#define NTHR 128
// fold 1/sqrt(64) * log2(e) into Q so scores are in log2 domain
#define QSCALE 0.1803368801111244f

// ============================ device scratch ============================
__device__ __half g_Kh[BH * SEQ * DIM];   // K, fp16
__device__ __half g_Lh[BH * SEQ * DIM];   // log_sigmoid(V), fp16
// permuted mask bits: [b][row][it][quad] u32; bit(2i+z) = mask[b][row][it*128 + i*8 + 2*quad + z]
__device__ unsigned g_Mp[8 * SEQ * NIT * 4];

// ============================ PTX helpers ============================
__device__ __forceinline__ uint32_t smem_u32(const void* p) {
    uint32_t a;
    asm("{ .reg .u64 t; cvta.to.shared.u64 t, %1; cvt.u32.u64 %0, t; }"
        : "=r"(a) : "l"(p));
    return a;
}
__device__ __forceinline__ uint32_t swz(uint32_t o) { return o ^ ((o >> 3) & 0x70); }

__device__ __forceinline__ void ldmx4(uint32_t& r0, uint32_t& r1, uint32_t& r2,
                                      uint32_t& r3, uint32_t a) {
    asm volatile("ldmatrix.sync.aligned.m8n8.x4.shared.b16 {%0,%1,%2,%3}, [%4];"
        : "=r"(r0), "=r"(r1), "=r"(r2), "=r"(r3) : "r"(a));
}
__device__ __forceinline__ void ldmx4t(uint32_t& r0, uint32_t& r1, uint32_t& r2,
                                       uint32_t& r3, uint32_t a) {
    asm volatile("ldmatrix.sync.aligned.m8n8.x4.trans.shared.b16 {%0,%1,%2,%3}, [%4];"
        : "=r"(r0), "=r"(r1), "=r"(r2), "=r"(r3) : "r"(a));
}
// NON-volatile: pure register op; lets ptxas pipeline ldmatrix over mma groups
__device__ __forceinline__ void mma_f16(float* c, const uint32_t* a,
                                        uint32_t b0, uint32_t b1) {
    asm("mma.sync.aligned.m16n8k16.row.col.f32.f16.f16.f32 "
        "{%0,%1,%2,%3}, {%4,%5,%6,%7}, {%8,%9}, {%0,%1,%2,%3};"
        : "+f"(c[0]), "+f"(c[1]), "+f"(c[2]), "+f"(c[3])
        : "r"(a[0]), "r"(a[1]), "r"(a[2]), "r"(a[3]), "r"(b0), "r"(b1));
}
__device__ __forceinline__ uint32_t pack_h2(float lo, float hi) {
    uint32_t r;
    asm("cvt.rn.f16x2.f32 %0, %1, %2;" : "=r"(r) : "f"(hi), "f"(lo));
    return r;
}
__device__ __forceinline__ float ex2(float x) {
    float r;
    asm("ex2.approx.ftz.f32 %0, %1;" : "=f"(r) : "f"(x));
    return r;
}
__device__ __forceinline__ void cp16(uint32_t s, const void* g) {
    asm volatile("cp.async.cg.shared.global [%0], [%1], 16;" :: "r"(s), "l"(g));
}
#define CP_COMMIT() asm volatile("cp.async.commit_group;" ::: "memory")
#define CP_WAIT(n)  asm volatile("cp.async.wait_group %0;" :: "n"(n) : "memory")

// ============================ fused preprocessing ============================
// blocks [0, 1024): mask bit-permute, one thread per output word (quad).
// blocks [1024, 9216): K -> fp16, log_sigmoid(V) -> fp16.
#define MASK_BLOCKS 1024
__global__ void prep_all(const void* __restrict__ msrc,
                         const float4* __restrict__ K,
                         const float4* __restrict__ V) {
    if (blockIdx.x < MASK_BLOCKS) {
        int idx = blockIdx.x * 256 + threadIdx.x;   // 262144 words
        int q = idx & 3;
        int chunk = idx >> 2;                        // 65536 chunks of 128 elems
        size_t ebase = (size_t)chunk * 128;          // element index (mask is [b*1024+row][1024])
        // dtype detect: each thread checks 16B of its chunk region (in-bounds for both dtypes)
        uint4 d = ((const uint4*)msrc)[ebase / 16 + q];
        int ok = (d.x==0u||d.x==1u||d.x==0x3F800000u) && (d.y==0u||d.y==1u||d.y==0x3F800000u)
              && (d.z==0u||d.z==1u||d.z==0x3F800000u) && (d.w==0u||d.w==1u||d.w==0x3F800000u);
        int wide = __syncthreads_and(ok);
        unsigned w = 0;
        if (wide) {
            // int32/float32 elems: pair (8i+2q, 8i+2q+1) = one uint2, stride 4 uint2
            const uint2* s = (const uint2*)msrc + ebase / 2 + q;
#pragma unroll
            for (int i = 0; i < 16; i++) {
                uint2 a = s[i * 4];
                w |= ((a.x ? 1u : 0u) << (2 * i)) | ((a.y ? 1u : 0u) << (2 * i + 1));
            }
        } else {
            // byte elems: pair = one ushort, stride 4 ushort
            const unsigned short* s = (const unsigned short*)msrc + ebase / 2 + q;
#pragma unroll
            for (int i = 0; i < 16; i++) {
                unsigned v = s[i * 4];
                w |= (((v & 0xffu) ? 1u : 0u) << (2 * i)) | (((v >> 8) ? 1u : 0u) << (2 * i + 1));
            }
        }
        g_Mp[(size_t)chunk * 4 + q] = w;
    } else {
        int i = (blockIdx.x - MASK_BLOCKS) * 256 + threadIdx.x;
        float4 k = K[i];
        __half2* ko = (__half2*)g_Kh;
        ko[2 * i]     = __floats2half2_rn(k.x, k.y);
        ko[2 * i + 1] = __floats2half2_rn(k.z, k.w);
        float4 v = V[i];
        float a0 = fminf(v.x, 0.f) - log1pf(__expf(-fabsf(v.x)));
        float a1 = fminf(v.y, 0.f) - log1pf(__expf(-fabsf(v.y)));
        float a2 = fminf(v.z, 0.f) - log1pf(__expf(-fabsf(v.z)));
        float a3 = fminf(v.w, 0.f) - log1pf(__expf(-fabsf(v.w)));
        __half2* lo = (__half2*)g_Lh;
        lo[2 * i]     = __floats2half2_rn(a0, a1);
        lo[2 * i + 1] = __floats2half2_rn(a2, a3);
    }
}

// ============================ attention kernel ============================
// smem: 2 stages x (K tile 16KB + L tile 16KB) = 64KB; rows 128B, SW128 swizzle
#define ST_K(s) ((s) * 32768)
#define ST_L(s) ((s) * 32768 + 16384)
#define SMEM_BYTES 65536

__device__ __forceinline__ void prefetch_tiles(int st, int t,
                                               const __half* Kb, const __half* Lb,
                                               int k0, uint32_t sb) {
#pragma unroll
    for (int i = t; i < 1024; i += NTHR) {
        int r = i >> 3, j = i & 7;
        cp16(sb + ST_K(st) + swz(r * 128 + j * 16), Kb + (size_t)(k0 + r) * DIM + j * 8);
    }
#pragma unroll
    for (int i = t; i < 1024; i += NTHR) {
        int r = i >> 3, j = i & 7;
        cp16(sb + ST_L(st) + swz(r * 128 + j * 16), Lb + (size_t)(k0 + r) * DIM + j * 8);
    }
}

__global__ void __launch_bounds__(NTHR, 3)
attn_kernel(const float* __restrict__ Q, float* __restrict__ out) {
    extern __shared__ char smem[];
    const uint32_t sb = smem_u32(smem);
    const int t = threadIdx.x, w = t >> 5, lane = t & 31;
    const int bh = blockIdx.y, q0 = blockIdx.x * QT;
    const int b = bh >> 4;

    const __half* Kbh = g_Kh + (size_t)bh * SEQ * DIM;
    const __half* Lbh = g_Lh + (size_t)bh * SEQ * DIM;

    // ---- Q tile: fp32 LDG -> fp16 convert (fold scale*log2e) -> smem stage0 ----
    {
        const float4* Qs = (const float4*)(Q + ((size_t)bh * SEQ + q0) * DIM);
#pragma unroll
        for (int i = t; i < 1024; i += NTHR) {   // 64 rows x 16 float4
            int r = i >> 4, j = i & 15;
            float4 q = Qs[i];
            uint2 hv;
            hv.x = pack_h2(q.x * QSCALE, q.y * QSCALE);
            hv.y = pack_h2(q.z * QSCALE, q.w * QSCALE);
            *(uint2*)(smem + ST_K(0) + swz(r * 128 + j * 8)) = hv;
        }
    }
    __syncthreads();

    const uint32_t xr = (uint32_t)(lane & 7) << 4;   // swizzle XOR (row&7)<<4
    uint32_t qf[4][4];
    {
        uint32_t base = sb + ST_K(0) + (uint32_t)(16 * w + (lane & 15)) * 128;
        uint32_t ch = (uint32_t)(lane >> 4) << 4;    // +16B for k8..15 octets
#pragma unroll
        for (int kd = 0; kd < 4; kd++)
            ldmx4(qf[kd][0], qf[kd][1], qf[kd][2], qf[kd][3],
                  base + (((uint32_t)kd * 32 + ch) ^ xr));
    }
    __syncthreads();

    // permuted mask words: one u32 per (row, it); this thread's quad = lane&3
    const unsigned* mp0 = g_Mp + ((size_t)(b * 1024 + q0 + 16 * w + (lane >> 2)) * NIT) * 4 + (lane & 3);
    const unsigned* mp1 = mp0 + 8 * NIT * 4;         // +8 rows

    // per-thread ldmatrix base offsets
    const uint32_t rbK = (uint32_t)((lane & 7) + ((lane >> 4) << 3));       // K B-frag rows
    const uint32_t csK = (uint32_t)(((lane >> 3) & 1) << 4);                // K col sel
    const uint32_t rbL = (uint32_t)((lane & 7) + (((lane >> 3) & 1) << 3)); // L rows
    const uint32_t csL = (uint32_t)(((lane >> 4) & 1) << 4);                // L col sel

    float oacc[8][4];
#pragma unroll
    for (int j = 0; j < 8; j++)
#pragma unroll
        for (int x = 0; x < 4; x++) oacc[j][x] = 0.f;
    float den0 = 0.f, den1 = 0.f;

    prefetch_tiles(0, t, Kbh, Lbh, 0, sb);
    CP_COMMIT();

    for (int it = 0; it < NIT; it++) {
        const int st = it & 1;
        if (it < NIT - 1) {
            prefetch_tiles(st ^ 1, t, Kbh, Lbh, (it + 1) * KT, sb);
            CP_COMMIT();
            CP_WAIT(1);
        } else {
            CP_WAIT(0);
        }
        __syncthreads();

        const unsigned mw0 = mp0[it * 4], mw1 = mp1[it * 4];
        const uint32_t baseK = sb + ST_K(st) + rbK * 128;
        const uint32_t baseL = sb + ST_L(st) + rbL * 128;

#pragma unroll
        for (int h = 0; h < 2; h++) {            // two 64-col halves
            // ---- GEMM1 half: S[16x64] = Q @ K^T ----
            float c[8][4];
#pragma unroll
            for (int j = 0; j < 8; j++)
#pragma unroll
                for (int x = 0; x < 4; x++) c[j][x] = 0.f;
#pragma unroll
            for (int jp = 0; jp < 4; jp++) {
                const uint32_t ko = (uint32_t)(h * 4 + jp) * 2048;
                uint32_t bfr[4][4];
#pragma unroll
                for (int kd = 0; kd < 4; kd++)
                    ldmx4(bfr[kd][0], bfr[kd][1], bfr[kd][2], bfr[kd][3],
                          baseK + ko + (((uint32_t)kd * 32 + csK) ^ xr));
#pragma unroll
                for (int kd = 0; kd < 4; kd++) {
                    mma_f16(c[2 * jp],     qf[kd], bfr[kd][0], bfr[kd][1]);
                    mma_f16(c[2 * jp + 1], qf[kd], bfr[kd][2], bfr[kd][3]);
                }
            }

            // ---- epilogue half: P = mask * 2^S (scores already in log2 domain) ----
            const unsigned ma = mw0 >> (16 * h), mb = mw1 >> (16 * h);
            uint32_t p2[8][2];
#pragma unroll
            for (int j = 0; j < 8; j++) {
                unsigned ba = ma >> (2 * j), bb = mb >> (2 * j);
                float s0 = (ba & 1u) ? c[j][0] : -127.f;
                float s1 = (ba & 2u) ? c[j][1] : -127.f;
                float s2 = (bb & 1u) ? c[j][2] : -127.f;
                float s3 = (bb & 2u) ? c[j][3] : -127.f;
                float e0 = ex2(s0), e1 = ex2(s1);
                float e2 = ex2(s2), e3 = ex2(s3);
                den0 += e0 + e1;
                den1 += e2 + e3;
                p2[j][0] = pack_h2(e0, e1);
                p2[j][1] = pack_h2(e2, e3);
            }

            // ---- GEMM2 half: O[16x64] += P @ L (k rows h*64..h*64+63) ----
#pragma unroll
            for (int kk = 0; kk < 4; kk++) {
                const uint32_t ko = (uint32_t)(h * 4 + kk) * 2048;
                uint32_t a[4] = {p2[2 * kk][0], p2[2 * kk][1],
                                 p2[2 * kk + 1][0], p2[2 * kk + 1][1]};
#pragma unroll
                for (int dp = 0; dp < 4; dp++) {
                    uint32_t b0, b1, b2, b3;
                    ldmx4t(b0, b1, b2, b3,
                           baseL + ko + (((uint32_t)dp * 32 + csL) ^ xr));
                    mma_f16(oacc[2 * dp],     a, b0, b1);
                    mma_f16(oacc[2 * dp + 1], a, b2, b3);
                }
            }
        }
        __syncthreads();
    }

    // ---- final: quad-reduce den, normalize, exp, store ----
    den0 += __shfl_xor_sync(0xffffffffu, den0, 1);
    den0 += __shfl_xor_sync(0xffffffffu, den0, 2);
    den1 += __shfl_xor_sync(0xffffffffu, den1, 1);
    den1 += __shfl_xor_sync(0xffffffffu, den1, 2);
    const float inv0 = 1.f / den0, inv1 = 1.f / den1;

    const int cb = 2 * (lane & 3);
    const int r0 = q0 + 16 * w + (lane >> 2);
    float* o0 = out + ((size_t)bh * SEQ + r0) * DIM + cb;
    float* o1 = o0 + 8 * DIM;
#pragma unroll
    for (int j = 0; j < 8; j++) {
        float2 v0, v1;
        v0.x = __expf(oacc[j][0] * inv0);
        v0.y = __expf(oacc[j][1] * inv0);
        v1.x = __expf(oacc[j][2] * inv1);
        v1.y = __expf(oacc[j][3] * inv1);
        *(float2*)(o0 + 8 * j) = v0;
        *(float2*)(o1 + 8 * j) = v1;
    }
}

// ============================ launch ============================
extern "C" void kernel_launch(void* const* d_in, const int* in_sizes, int n_in,
                              void* d_out, int out_size) {
    const float* Q = (const float*)d_in[0];
    const float* K = (const float*)d_in[1];
    const float* V = (const float*)d_in[2];
    const void*  M = d_in[3];
    float* out = (float*)d_out;

    prep_all<<<MASK_BLOCKS + 8192, 256>>>(M, (const float4*)K, (const float4*)V);

    cudaFuncSetAttribute(attn_kernel,
                         cudaFuncAttributeMaxDynamicSharedMemorySize, SMEM_BYTES);
    dim3 grid(SEQ / QT, BH);
    attn_kernel<<<grid, NTHR, SMEM_BYTES>>>(Q, out);
}